// round 6
// baseline (speedup 1.0000x reference)
#include <cuda_runtime.h>
#include <math.h>

#define D        512
#define BMAX     16
#define NCTOT    296          // total k2 chunks == 2 blocks per SM (148 SMs)
#define NCMAX    19           // max chunks per batch
#define NEG_INF  -1e30f

// ---------------- scratch (no allocation allowed) ----------------
__device__ float g_q[BMAX * D];                    // q = query @ W_align^T + b_align
__device__ float g_pm[BMAX * NCMAX];               // per-chunk running max
__device__ float g_ps[BMAX * NCMAX];               // per-chunk denom (rel. to g_pm)
__device__ float g_pctx[BMAX * NCMAX * D];         // per-chunk partial context
__device__ float g_ctx[BMAX * D];                  // combined, normalized context

// ---------------- K1: q = query @ W_align^T + b_align ----------------
// grid = (D/4, B/4), block = 256 (8 warps).
// Warp = (one output dim, one K-half, 4 batches): 2 W float4 + 8 query float4
// per lane, all independent. 4096 warps total. K-halves combined via smem.
__global__ void __launch_bounds__(256) k1_qproj(
    const float* __restrict__ query,
    const float* __restrict__ W_align,
    const float* __restrict__ b_align)
{
    const int w    = threadIdx.x >> 5;
    const int lane = threadIdx.x & 31;
    const int d    = blockIdx.x * 4 + (w & 3);
    const int kh   = w >> 2;                  // K-half 0/1
    const int b0   = blockIdx.y * 4;

    const float4* wrow = reinterpret_cast<const float4*>(W_align + (size_t)d * D);
    float4 wa[2];
#pragma unroll
    for (int j = 0; j < 2; j++) wa[j] = wrow[lane + 32 * (2 * kh + j)];

    float acc[4] = {0.f, 0.f, 0.f, 0.f};
#pragma unroll
    for (int jb = 0; jb < 4; jb++) {
        const float4* xq = reinterpret_cast<const float4*>(query + (size_t)(b0 + jb) * D);
#pragma unroll
        for (int j = 0; j < 2; j++) {
            float4 x = xq[lane + 32 * (2 * kh + j)];
            acc[jb] = fmaf(wa[j].x, x.x, acc[jb]); acc[jb] = fmaf(wa[j].y, x.y, acc[jb]);
            acc[jb] = fmaf(wa[j].z, x.z, acc[jb]); acc[jb] = fmaf(wa[j].w, x.w, acc[jb]);
        }
    }
#pragma unroll
    for (int o = 16; o > 0; o >>= 1) {
#pragma unroll
        for (int jb = 0; jb < 4; jb++) acc[jb] += __shfl_xor_sync(0xffffffffu, acc[jb], o);
    }
    __shared__ float sp[8][4];
#pragma unroll
    for (int jb = 0; jb < 4; jb++)
        if (lane == jb) sp[w][jb] = acc[jb];
    __syncthreads();
    if (w < 4 && lane < 4) {
        const int dd = blockIdx.x * 4 + w;
        g_q[(size_t)(b0 + lane) * D + dd] = sp[w][lane] + sp[w + 4][lane] + b_align[dd];
    }
}

// ---------------- K2: single-pass online-softmax over value ----------------
// grid = NCTOT (exactly 2 blocks per SM), block = 256 (8 warps), <=2 blocks/SM.
// Chunks distributed: first (NCTOT%B) batches get base+1 chunks, rest base.
// Block compacts unmasked rows of its chunk into smem; warps consume them in
// a statically balanced interleave, 4 rows per iteration.
__global__ void __launch_bounds__(256, 2) k2_attn(
    const float* __restrict__ value,
    const int*   __restrict__ mask,
    int L, int B)
{
    const int base = NCTOT / B;               // 18
    const int rem  = NCTOT % B;               // 8
    const int thr  = rem * (base + 1);        // 152
    int b, c, NC;
    if ((int)blockIdx.x < thr) { b = blockIdx.x / (base + 1); c = blockIdx.x % (base + 1); NC = base + 1; }
    else { const int t = blockIdx.x - thr; b = rem + t / base; c = t % base; NC = base; }
    const int CS  = (L + NC - 1) / NC;
    const int l0  = c * CS;
    const int len = min(CS, L - l0);           // <= 512

    const int tid  = threadIdx.x;
    const int warp = tid >> 5;
    const int lane = tid & 31;

    __shared__ int s_idx[512];
    __shared__ int s_pop[16], s_off[16], s_total;

    // ---- compact unmasked row indices (deterministic) ----
    const int* mrow = mask + (size_t)b * L + l0;
    const int i0 = tid, i1 = tid + 256;
    unsigned a0 = __ballot_sync(0xffffffffu, (i0 < len) && (mrow[i0] == 0));
    unsigned a1 = __ballot_sync(0xffffffffu, (i1 < len) && (mrow[i1] == 0));
    if (lane == 0) { s_pop[warp] = __popc(a0); s_pop[warp + 8] = __popc(a1); }
    __syncthreads();
    if (tid == 0) {
        int acc = 0;
#pragma unroll
        for (int i = 0; i < 16; i++) { s_off[i] = acc; acc += s_pop[i]; }
        s_total = acc;
    }
    __syncthreads();
    if ((a0 >> lane) & 1)
        s_idx[s_off[warp]     + __popc(a0 & ((1u << lane) - 1))] = warp * 32 + lane;
    if ((a1 >> lane) & 1)
        s_idx[s_off[warp + 8] + __popc(a1 & ((1u << lane) - 1))] = 256 + warp * 32 + lane;
    __syncthreads();
    const int T = s_total;

    // ---- q into registers (float4-strided) ----
    const float4* q4 = reinterpret_cast<const float4*>(g_q + b * D);
    float4 q[4];
#pragma unroll
    for (int k = 0; k < 4; k++) q[k] = q4[lane + 32 * k];

    float m = NEG_INF, s = 0.f;
    float4 ctx[4];
#pragma unroll
    for (int k = 0; k < 4; k++) ctx[k] = make_float4(0.f, 0.f, 0.f, 0.f);

    const float* vbase = value + ((size_t)b * L + l0) * D;

    for (int t0 = warp * 4; t0 < T; t0 += 32) {
        const int n = min(4, T - t0);
        const int j0 = s_idx[t0];
        const int j1 = s_idx[t0 + (n > 1 ? 1 : 0)];
        const int j2 = s_idx[t0 + (n > 2 ? 2 : 0)];
        const int j3 = s_idx[t0 + (n > 3 ? 3 : 0)];

        const float4* p0 = reinterpret_cast<const float4*>(vbase + (size_t)j0 * D);
        const float4* p1 = reinterpret_cast<const float4*>(vbase + (size_t)j1 * D);
        const float4* p2 = reinterpret_cast<const float4*>(vbase + (size_t)j2 * D);
        const float4* p3 = reinterpret_cast<const float4*>(vbase + (size_t)j3 * D);

        float4 v0[4], v1[4], v2[4], v3[4];
#pragma unroll
        for (int k = 0; k < 4; k++) v0[k] = __ldcs(p0 + lane + 32 * k);
#pragma unroll
        for (int k = 0; k < 4; k++) v1[k] = __ldcs(p1 + lane + 32 * k);
#pragma unroll
        for (int k = 0; k < 4; k++) v2[k] = __ldcs(p2 + lane + 32 * k);
#pragma unroll
        for (int k = 0; k < 4; k++) v3[k] = __ldcs(p3 + lane + 32 * k);

        float s0 = 0.f, s1 = 0.f, s2 = 0.f, s3 = 0.f;
#pragma unroll
        for (int k = 0; k < 4; k++) {
            s0 = fmaf(v0[k].x, q[k].x, s0); s0 = fmaf(v0[k].y, q[k].y, s0);
            s0 = fmaf(v0[k].z, q[k].z, s0); s0 = fmaf(v0[k].w, q[k].w, s0);
            s1 = fmaf(v1[k].x, q[k].x, s1); s1 = fmaf(v1[k].y, q[k].y, s1);
            s1 = fmaf(v1[k].z, q[k].z, s1); s1 = fmaf(v1[k].w, q[k].w, s1);
            s2 = fmaf(v2[k].x, q[k].x, s2); s2 = fmaf(v2[k].y, q[k].y, s2);
            s2 = fmaf(v2[k].z, q[k].z, s2); s2 = fmaf(v2[k].w, q[k].w, s2);
            s3 = fmaf(v3[k].x, q[k].x, s3); s3 = fmaf(v3[k].y, q[k].y, s3);
            s3 = fmaf(v3[k].z, q[k].z, s3); s3 = fmaf(v3[k].w, q[k].w, s3);
        }
#pragma unroll
        for (int o = 16; o > 0; o >>= 1) {
            s0 += __shfl_xor_sync(0xffffffffu, s0, o);
            s1 += __shfl_xor_sync(0xffffffffu, s1, o);
            s2 += __shfl_xor_sync(0xffffffffu, s2, o);
            s3 += __shfl_xor_sync(0xffffffffu, s3, o);
        }
        if (n < 2) s1 = NEG_INF;
        if (n < 3) s2 = NEG_INF;
        if (n < 4) s3 = NEG_INF;

        const float m_new = fmaxf(fmaxf(m, fmaxf(s0, s1)), fmaxf(s2, s3));
        const float corr = __expf(m  - m_new);
        const float w0   = __expf(s0 - m_new);
        const float w1   = __expf(s1 - m_new);
        const float w2   = __expf(s2 - m_new);
        const float w3   = __expf(s3 - m_new);
        s = s * corr + w0 + w1 + w2 + w3;
#pragma unroll
        for (int k = 0; k < 4; k++) {
            ctx[k].x = ctx[k].x * corr + fmaf(w1, v1[k].x, w0 * v0[k].x)
                                       + fmaf(w3, v3[k].x, w2 * v2[k].x);
            ctx[k].y = ctx[k].y * corr + fmaf(w1, v1[k].y, w0 * v0[k].y)
                                       + fmaf(w3, v3[k].y, w2 * v2[k].y);
            ctx[k].z = ctx[k].z * corr + fmaf(w1, v1[k].z, w0 * v0[k].z)
                                       + fmaf(w3, v3[k].z, w2 * v2[k].z);
            ctx[k].w = ctx[k].w * corr + fmaf(w1, v1[k].w, w0 * v0[k].w)
                                       + fmaf(w3, v3[k].w, w2 * v2[k].w);
        }
        m = m_new;
    }

    // ---- merge the 8 warps' partials ----
    __shared__ float sm_m[8], sm_s[8];
    __shared__ float sm_ctx[8][D];
    if (lane == 0) { sm_m[warp] = m; sm_s[warp] = s; }
#pragma unroll
    for (int k = 0; k < 4; k++) {
        const int i = (lane + 32 * k) * 4;
        sm_ctx[warp][i + 0] = ctx[k].x;
        sm_ctx[warp][i + 1] = ctx[k].y;
        sm_ctx[warp][i + 2] = ctx[k].z;
        sm_ctx[warp][i + 3] = ctx[k].w;
    }
    __syncthreads();

    float M = NEG_INF;
#pragma unroll
    for (int wi = 0; wi < 8; wi++) M = fmaxf(M, sm_m[wi]);

    float e[8];
#pragma unroll
    for (int wi = 0; wi < 8; wi++) e[wi] = __expf(sm_m[wi] - M);

    float o0 = 0.f, o1 = 0.f;
#pragma unroll
    for (int wi = 0; wi < 8; wi++) {
        o0 = fmaf(sm_ctx[wi][tid],       e[wi], o0);
        o1 = fmaf(sm_ctx[wi][tid + 256], e[wi], o1);
    }
    const int pidx = b * NCMAX + c;
    g_pctx[(size_t)pidx * D + tid]       = o0;
    g_pctx[(size_t)pidx * D + tid + 256] = o1;

    if (tid == 0) {
        float S = 0.f;
#pragma unroll
        for (int wi = 0; wi < 8; wi++) S = fmaf(sm_s[wi], e[wi], S);
        g_pm[pidx] = M;
        g_ps[pidx] = S;
    }
}

// ---------------- K3a: combine chunk partials -> g_ctx (normalized) ----------------
// grid = (B, 2), block = 256. Each thread combines ONE d-column across the
// batch's chunks (MLP = NC independent loads).
__global__ void __launch_bounds__(256) k3a_combine(int B)
{
    const int b   = blockIdx.x;
    const int d   = blockIdx.y * 256 + threadIdx.x;
    const int tid = threadIdx.x;
    const int base = NCTOT / B;
    const int rem  = NCTOT % B;
    const int NC   = base + (b < rem ? 1 : 0);

    __shared__ float e_sm[NCMAX];
    __shared__ float Sinv_sm;

    float M = NEG_INF;
    for (int c = 0; c < NC; c++) M = fmaxf(M, g_pm[b * NCMAX + c]);
    if (tid < NC)
        e_sm[tid] = __expf(g_pm[b * NCMAX + tid] - M);
    __syncthreads();

    if (tid == 0) {
        float S = 0.f;
        for (int c = 0; c < NC; c++) S = fmaf(g_ps[b * NCMAX + c], e_sm[c], S);
        Sinv_sm = 1.f / S;
    }
    __syncthreads();
    const float Sinv = Sinv_sm;

    float acc = 0.f;
    for (int c = 0; c < NC; c++)
        acc = fmaf(g_pctx[((size_t)b * NCMAX + c) * D + d], e_sm[c], acc);
    g_ctx[(size_t)b * D + d] = acc * Sinv;
}

// ---------------- K3b: out = tanh(ctx@Wv^T + bv + q@Wq^T + bq) ----------------
// grid = (D/4, B/4), block = 256 (8 warps).
// Warp = (one output dim, one K-half, 4 batches): 4 W float4 + 16 x float4
// per lane, all independent. 4096 warps. K-halves combined via smem.
__global__ void __launch_bounds__(256) k3b_out(
    const float* __restrict__ W_query,
    const float* __restrict__ b_query,
    const float* __restrict__ W_value,
    const float* __restrict__ b_value,
    float* __restrict__ out)
{
    const int w    = threadIdx.x >> 5;
    const int lane = threadIdx.x & 31;
    const int d    = blockIdx.x * 4 + (w & 3);
    const int kh   = w >> 2;                  // K-half 0/1
    const int b0   = blockIdx.y * 4;

    const float4* wvp = reinterpret_cast<const float4*>(W_value + (size_t)d * D);
    const float4* wqp = reinterpret_cast<const float4*>(W_query + (size_t)d * D);
    float4 wv[2], wq[2];
#pragma unroll
    for (int j = 0; j < 2; j++) {
        wv[j] = wvp[lane + 32 * (2 * kh + j)];
        wq[j] = wqp[lane + 32 * (2 * kh + j)];
    }

    float acc[4] = {0.f, 0.f, 0.f, 0.f};
#pragma unroll
    for (int jb = 0; jb < 4; jb++) {
        const float4* cxp = reinterpret_cast<const float4*>(g_ctx + (size_t)(b0 + jb) * D);
        const float4* qxp = reinterpret_cast<const float4*>(g_q   + (size_t)(b0 + jb) * D);
#pragma unroll
        for (int j = 0; j < 2; j++) {
            float4 cx = cxp[lane + 32 * (2 * kh + j)];
            float4 qx = qxp[lane + 32 * (2 * kh + j)];
            acc[jb] = fmaf(wv[j].x, cx.x, acc[jb]); acc[jb] = fmaf(wv[j].y, cx.y, acc[jb]);
            acc[jb] = fmaf(wv[j].z, cx.z, acc[jb]); acc[jb] = fmaf(wv[j].w, cx.w, acc[jb]);
            acc[jb] = fmaf(wq[j].x, qx.x, acc[jb]); acc[jb] = fmaf(wq[j].y, qx.y, acc[jb]);
            acc[jb] = fmaf(wq[j].z, qx.z, acc[jb]); acc[jb] = fmaf(wq[j].w, qx.w, acc[jb]);
        }
    }
#pragma unroll
    for (int o = 16; o > 0; o >>= 1) {
#pragma unroll
        for (int jb = 0; jb < 4; jb++) acc[jb] += __shfl_xor_sync(0xffffffffu, acc[jb], o);
    }
    __shared__ float sp[8][4];
#pragma unroll
    for (int jb = 0; jb < 4; jb++)
        if (lane == jb) sp[w][jb] = acc[jb];
    __syncthreads();
    if (w < 4 && lane < 4) {
        const int dd = blockIdx.x * 4 + w;
        const float r = sp[w][lane] + sp[w + 4][lane];
        out[(size_t)(b0 + lane) * D + dd] = tanhf(r + b_value[dd] + b_query[dd]);
    }
}

// ---------------- launch ----------------
extern "C" void kernel_launch(void* const* d_in, const int* in_sizes, int n_in,
                              void* d_out, int out_size)
{
    const float* query   = (const float*)d_in[0];
    const float* value   = (const float*)d_in[1];
    const int*   mask    = (const int*)  d_in[2];
    const float* W_align = (const float*)d_in[3];
    const float* b_align = (const float*)d_in[4];
    const float* W_query = (const float*)d_in[5];
    const float* b_query = (const float*)d_in[6];
    const float* W_value = (const float*)d_in[7];
    const float* b_value = (const float*)d_in[8];
    float* out = (float*)d_out;

    const int B = in_sizes[0] / D;          // 16
    const int L = in_sizes[2] / B;          // 8192

    k1_qproj   <<<dim3(D / 4, B / 4), 256>>>(query, W_align, b_align);
    k2_attn    <<<NCTOT, 256>>>(value, mask, L, B);
    k3a_combine<<<dim3(B, 2), 256>>>(B);
    k3b_out    <<<dim3(D / 4, B / 4), 256>>>(W_query, b_query, W_value, b_value, out);
}

// round 7
// speedup vs baseline: 1.0026x; 1.0026x over previous
#include <cuda_runtime.h>
#include <math.h>

#define D        512
#define BMAX     16
#define NCHUNK   16
#define NEG_INF  -1e30f

// ---------------- scratch (no allocation allowed) ----------------
__device__ float g_q[BMAX * D];                    // q = query @ W_align^T + b_align
__device__ float g_pm[BMAX * NCHUNK];              // per-chunk running max
__device__ float g_ps[BMAX * NCHUNK];              // per-chunk denom (rel. to g_pm)
__device__ float g_pctx[BMAX * NCHUNK * D];        // per-chunk partial context

// ---------------- K1: q = query @ W_align^T + b_align ----------------
// grid = (D/32, B/4) = (16,4), block = 512 (16 warps).
// Block caches 4 query rows in smem; each warp computes 2 output dims for all
// 4 batches, streaming only the W rows (8 independent LDG.128 per lane).
__global__ void __launch_bounds__(512) k1_qproj(
    const float* __restrict__ query,
    const float* __restrict__ W_align,
    const float* __restrict__ b_align)
{
    const int tid  = threadIdx.x;
    const int warp = tid >> 5;
    const int lane = tid & 31;
    const int by0  = blockIdx.y * 4;

    __shared__ float s_x[4][D];
    for (int idx = tid; idx < 4 * D; idx += 512) {
        const int jb = idx >> 9, d = idx & (D - 1);
        s_x[jb][d] = query[(size_t)(by0 + jb) * D + d];
    }
    __syncthreads();

    const int d0 = blockIdx.x * 32 + warp * 2;
    float acc[2][4];
#pragma unroll
    for (int i = 0; i < 2; i++) {
        const float4* wrow = reinterpret_cast<const float4*>(W_align + (size_t)(d0 + i) * D);
        float4 w[4];
#pragma unroll
        for (int k = 0; k < 4; k++) w[k] = wrow[lane + 32 * k];
#pragma unroll
        for (int jb = 0; jb < 4; jb++) {
            const float4* x4 = reinterpret_cast<const float4*>(s_x[jb]);
            float a = 0.f;
#pragma unroll
            for (int k = 0; k < 4; k++) {
                float4 x = x4[lane + 32 * k];
                a = fmaf(w[k].x, x.x, a); a = fmaf(w[k].y, x.y, a);
                a = fmaf(w[k].z, x.z, a); a = fmaf(w[k].w, x.w, a);
            }
            acc[i][jb] = a;
        }
    }
#pragma unroll
    for (int o = 16; o > 0; o >>= 1) {
#pragma unroll
        for (int i = 0; i < 2; i++)
#pragma unroll
            for (int jb = 0; jb < 4; jb++)
                acc[i][jb] += __shfl_xor_sync(0xffffffffu, acc[i][jb], o);
    }
    if (lane < 4) {
#pragma unroll
        for (int i = 0; i < 2; i++)
            g_q[(size_t)(by0 + lane) * D + d0 + i] = acc[i][lane] + b_align[d0 + i];
    }
}

// ---------------- K2: single-pass online-softmax over value ----------------
// grid = B*NCHUNK (256 blocks = one resident wave), block = 256 (8 warps).
// Block compacts the unmasked rows of its 512-row chunk into smem, then warps
// consume them in a statically balanced interleave, 4 rows per iteration.
__global__ void __launch_bounds__(256) k2_attn(
    const float* __restrict__ value,
    const int*   __restrict__ mask,
    int L)
{
    const int b    = blockIdx.x / NCHUNK;
    const int c    = blockIdx.x % NCHUNK;
    const int RC   = L / NCHUNK;           // rows per chunk (512)
    const int l0   = c * RC;
    const int tid  = threadIdx.x;
    const int warp = tid >> 5;
    const int lane = tid & 31;

    __shared__ int   s_idx[512];
    __shared__ int   s_pop[16], s_off[16], s_total;

    // ---- compact unmasked row indices (deterministic) ----
    const int* mrow = mask + (size_t)b * L + l0;
    unsigned a0 = __ballot_sync(0xffffffffu, mrow[tid]       == 0);
    unsigned a1 = __ballot_sync(0xffffffffu, mrow[tid + 256] == 0);
    if (lane == 0) { s_pop[warp] = __popc(a0); s_pop[warp + 8] = __popc(a1); }
    __syncthreads();
    if (tid == 0) {
        int acc = 0;
#pragma unroll
        for (int i = 0; i < 16; i++) { s_off[i] = acc; acc += s_pop[i]; }
        s_total = acc;
    }
    __syncthreads();
    if ((a0 >> lane) & 1)
        s_idx[s_off[warp]     + __popc(a0 & ((1u << lane) - 1))] = warp * 32 + lane;
    if ((a1 >> lane) & 1)
        s_idx[s_off[warp + 8] + __popc(a1 & ((1u << lane) - 1))] = 256 + warp * 32 + lane;
    __syncthreads();
    const int T = s_total;

    // ---- q into registers (float4-strided) ----
    const float4* q4 = reinterpret_cast<const float4*>(g_q + b * D);
    float4 q[4];
#pragma unroll
    for (int k = 0; k < 4; k++) q[k] = q4[lane + 32 * k];

    float m = NEG_INF, s = 0.f;
    float4 ctx[4];
#pragma unroll
    for (int k = 0; k < 4; k++) ctx[k] = make_float4(0.f, 0.f, 0.f, 0.f);

    const float* vbase = value + ((size_t)b * L + l0) * D;

    for (int t0 = warp * 4; t0 < T; t0 += 32) {
        const int n = min(4, T - t0);
        const int j0 = s_idx[t0];
        const int j1 = s_idx[t0 + (n > 1 ? 1 : 0)];
        const int j2 = s_idx[t0 + (n > 2 ? 2 : 0)];
        const int j3 = s_idx[t0 + (n > 3 ? 3 : 0)];

        const float4* p0 = reinterpret_cast<const float4*>(vbase + (size_t)j0 * D);
        const float4* p1 = reinterpret_cast<const float4*>(vbase + (size_t)j1 * D);
        const float4* p2 = reinterpret_cast<const float4*>(vbase + (size_t)j2 * D);
        const float4* p3 = reinterpret_cast<const float4*>(vbase + (size_t)j3 * D);

        float4 v0[4], v1[4], v2[4], v3[4];
#pragma unroll
        for (int k = 0; k < 4; k++) v0[k] = __ldcs(p0 + lane + 32 * k);
#pragma unroll
        for (int k = 0; k < 4; k++) v1[k] = __ldcs(p1 + lane + 32 * k);
#pragma unroll
        for (int k = 0; k < 4; k++) v2[k] = __ldcs(p2 + lane + 32 * k);
#pragma unroll
        for (int k = 0; k < 4; k++) v3[k] = __ldcs(p3 + lane + 32 * k);

        float s0 = 0.f, s1 = 0.f, s2 = 0.f, s3 = 0.f;
#pragma unroll
        for (int k = 0; k < 4; k++) {
            s0 = fmaf(v0[k].x, q[k].x, s0); s0 = fmaf(v0[k].y, q[k].y, s0);
            s0 = fmaf(v0[k].z, q[k].z, s0); s0 = fmaf(v0[k].w, q[k].w, s0);
            s1 = fmaf(v1[k].x, q[k].x, s1); s1 = fmaf(v1[k].y, q[k].y, s1);
            s1 = fmaf(v1[k].z, q[k].z, s1); s1 = fmaf(v1[k].w, q[k].w, s1);
            s2 = fmaf(v2[k].x, q[k].x, s2); s2 = fmaf(v2[k].y, q[k].y, s2);
            s2 = fmaf(v2[k].z, q[k].z, s2); s2 = fmaf(v2[k].w, q[k].w, s2);
            s3 = fmaf(v3[k].x, q[k].x, s3); s3 = fmaf(v3[k].y, q[k].y, s3);
            s3 = fmaf(v3[k].w, q[k].w, s3); s3 = fmaf(v3[k].z, q[k].z, s3);
        }
#pragma unroll
        for (int o = 16; o > 0; o >>= 1) {
            s0 += __shfl_xor_sync(0xffffffffu, s0, o);
            s1 += __shfl_xor_sync(0xffffffffu, s1, o);
            s2 += __shfl_xor_sync(0xffffffffu, s2, o);
            s3 += __shfl_xor_sync(0xffffffffu, s3, o);
        }
        if (n < 2) s1 = NEG_INF;
        if (n < 3) s2 = NEG_INF;
        if (n < 4) s3 = NEG_INF;

        const float m_new = fmaxf(fmaxf(m, fmaxf(s0, s1)), fmaxf(s2, s3));
        const float corr = __expf(m  - m_new);
        const float w0   = __expf(s0 - m_new);
        const float w1   = __expf(s1 - m_new);
        const float w2   = __expf(s2 - m_new);
        const float w3   = __expf(s3 - m_new);
        s = s * corr + w0 + w1 + w2 + w3;
#pragma unroll
        for (int k = 0; k < 4; k++) {
            ctx[k].x = ctx[k].x * corr + fmaf(w1, v1[k].x, w0 * v0[k].x)
                                       + fmaf(w3, v3[k].x, w2 * v2[k].x);
            ctx[k].y = ctx[k].y * corr + fmaf(w1, v1[k].y, w0 * v0[k].y)
                                       + fmaf(w3, v3[k].y, w2 * v2[k].y);
            ctx[k].z = ctx[k].z * corr + fmaf(w1, v1[k].z, w0 * v0[k].z)
                                       + fmaf(w3, v3[k].z, w2 * v2[k].z);
            ctx[k].w = ctx[k].w * corr + fmaf(w1, v1[k].w, w0 * v0[k].w)
                                       + fmaf(w3, v3[k].w, w2 * v2[k].w);
        }
        m = m_new;
    }

    // ---- merge the 8 warps' partials ----
    __shared__ float sm_m[8], sm_s[8];
    __shared__ float sm_ctx[8][D];
    if (lane == 0) { sm_m[warp] = m; sm_s[warp] = s; }
#pragma unroll
    for (int k = 0; k < 4; k++) {
        const int i = (lane + 32 * k) * 4;
        sm_ctx[warp][i + 0] = ctx[k].x;
        sm_ctx[warp][i + 1] = ctx[k].y;
        sm_ctx[warp][i + 2] = ctx[k].z;
        sm_ctx[warp][i + 3] = ctx[k].w;
    }
    __syncthreads();

    float M = NEG_INF;
#pragma unroll
    for (int wi = 0; wi < 8; wi++) M = fmaxf(M, sm_m[wi]);

    float e[8];
#pragma unroll
    for (int wi = 0; wi < 8; wi++) e[wi] = __expf(sm_m[wi] - M);

    float o0 = 0.f, o1 = 0.f;
#pragma unroll
    for (int wi = 0; wi < 8; wi++) {
        o0 = fmaf(sm_ctx[wi][tid],       e[wi], o0);
        o1 = fmaf(sm_ctx[wi][tid + 256], e[wi], o1);
    }
    const int pidx = b * NCHUNK + c;
    g_pctx[(size_t)pidx * D + tid]       = o0;
    g_pctx[(size_t)pidx * D + tid + 256] = o1;

    if (tid == 0) {
        float S = 0.f;
#pragma unroll
        for (int wi = 0; wi < 8; wi++) S = fmaf(sm_s[wi], e[wi], S);
        g_pm[pidx] = M;
        g_ps[pidx] = S;
    }
}

// ---------------- K3: fused combine + out = tanh(ctx@Wv^T + bv + q@Wq^T + bq) ----
// grid = (D/32, B/4) = (16,4), block = 512 (16 warps).
// Phase 1: block combines the 16 chunk partials for its 4 batches into smem
// (normalized context) and caches q. Phase 2: each warp computes 2 output
// dims for all 4 batches, streaming only the Wv/Wq rows.
__global__ void __launch_bounds__(512) k3_out(
    const float* __restrict__ W_query,
    const float* __restrict__ b_query,
    const float* __restrict__ W_value,
    const float* __restrict__ b_value,
    float* __restrict__ out)
{
    const int tid  = threadIdx.x;
    const int warp = tid >> 5;
    const int lane = tid & 31;
    const int by0  = blockIdx.y * 4;

    __shared__ float s_ctx[4][D];
    __shared__ float s_q[4][D];
    __shared__ float s_e[4][NCHUNK];
    __shared__ float s_Sinv[4];

    // ---- per-batch softmax-combine factors (warps 0..3, one batch each) ----
    if (warp < 4) {
        const int b = by0 + warp;
        float mv = (lane < NCHUNK) ? g_pm[b * NCHUNK + lane] : NEG_INF;
        float M = mv;
#pragma unroll
        for (int o = 16; o > 0; o >>= 1) M = fmaxf(M, __shfl_xor_sync(0xffffffffu, M, o));
        float e = (lane < NCHUNK) ? __expf(mv - M) : 0.f;
        float Sp = (lane < NCHUNK) ? g_ps[b * NCHUNK + lane] * e : 0.f;
#pragma unroll
        for (int o = 16; o > 0; o >>= 1) Sp += __shfl_xor_sync(0xffffffffu, Sp, o);
        if (lane < NCHUNK) s_e[warp][lane] = e;
        if (lane == 0) s_Sinv[warp] = 1.f / Sp;
    }
    __syncthreads();

    // ---- combine partial contexts into smem (normalized); cache q ----
    for (int idx = tid; idx < 4 * D; idx += 512) {
        const int jb = idx >> 9, d = idx & (D - 1);
        const int b = by0 + jb;
        const float* pc = g_pctx + (size_t)b * NCHUNK * D + d;
        float acc = 0.f;
#pragma unroll
        for (int c = 0; c < NCHUNK; c++)
            acc = fmaf(pc[(size_t)c * D], s_e[jb][c], acc);
        s_ctx[jb][d] = acc * s_Sinv[jb];
        s_q[jb][d]   = g_q[(size_t)b * D + d];
    }
    __syncthreads();

    // ---- dual GEMV + tanh ----
    const int d0 = blockIdx.x * 32 + warp * 2;
    float acc[2][4];
#pragma unroll
    for (int i = 0; i < 2; i++) {
        const float4* wvp = reinterpret_cast<const float4*>(W_value + (size_t)(d0 + i) * D);
        const float4* wqp = reinterpret_cast<const float4*>(W_query + (size_t)(d0 + i) * D);
        float4 wv[4], wq[4];
#pragma unroll
        for (int k = 0; k < 4; k++) { wv[k] = wvp[lane + 32 * k]; wq[k] = wqp[lane + 32 * k]; }
#pragma unroll
        for (int jb = 0; jb < 4; jb++) {
            const float4* c4 = reinterpret_cast<const float4*>(s_ctx[jb]);
            const float4* q4 = reinterpret_cast<const float4*>(s_q[jb]);
            float a = 0.f;
#pragma unroll
            for (int k = 0; k < 4; k++) {
                float4 cx = c4[lane + 32 * k];
                float4 qx = q4[lane + 32 * k];
                a = fmaf(wv[k].x, cx.x, a); a = fmaf(wv[k].y, cx.y, a);
                a = fmaf(wv[k].z, cx.z, a); a = fmaf(wv[k].w, cx.w, a);
                a = fmaf(wq[k].x, qx.x, a); a = fmaf(wq[k].y, qx.y, a);
                a = fmaf(wq[k].z, qx.z, a); a = fmaf(wq[k].w, qx.w, a);
            }
            acc[i][jb] = a;
        }
    }
#pragma unroll
    for (int o = 16; o > 0; o >>= 1) {
#pragma unroll
        for (int i = 0; i < 2; i++)
#pragma unroll
            for (int jb = 0; jb < 4; jb++)
                acc[i][jb] += __shfl_xor_sync(0xffffffffu, acc[i][jb], o);
    }
    if (lane < 4) {
#pragma unroll
        for (int i = 0; i < 2; i++) {
            const int d = d0 + i;
            out[(size_t)(by0 + lane) * D + d] =
                tanhf(acc[i][lane] + b_value[d] + b_query[d]);
        }
    }
}

// ---------------- launch ----------------
extern "C" void kernel_launch(void* const* d_in, const int* in_sizes, int n_in,
                              void* d_out, int out_size)
{
    const float* query   = (const float*)d_in[0];
    const float* value   = (const float*)d_in[1];
    const int*   mask    = (const int*)  d_in[2];
    const float* W_align = (const float*)d_in[3];
    const float* b_align = (const float*)d_in[4];
    const float* W_query = (const float*)d_in[5];
    const float* b_query = (const float*)d_in[6];
    const float* W_value = (const float*)d_in[7];
    const float* b_value = (const float*)d_in[8];
    float* out = (float*)d_out;

    const int B = in_sizes[0] / D;          // 16
    const int L = in_sizes[2] / B;          // 8192

    k1_qproj<<<dim3(D / 32, B / 4), 512>>>(query, W_align, b_align);
    k2_attn <<<B * NCHUNK, 256>>>(value, mask, L);
    k3_out  <<<dim3(D / 32, B / 4), 512>>>(W_query, b_query, W_value, b_value, out);
}

// round 8
// speedup vs baseline: 1.0776x; 1.0748x over previous
#include <cuda_runtime.h>
#include <math.h>

#define D        512
#define NCHUNK   16
#define BMAX     16
#define NEG_INF  -1e30f

// ---------------- scratch (no allocation allowed) ----------------
__device__ float g_q[BMAX * D];                    // q = query @ W_align^T + b_align
__device__ float g_pm[BMAX * NCHUNK];              // per-chunk running max
__device__ float g_ps[BMAX * NCHUNK];              // per-chunk denom (rel. to g_pm)
__device__ float g_pctx[BMAX * NCHUNK * D];        // per-chunk partial context
__device__ unsigned long long g_bar = 0;           // grid barrier ticket counter

// Replay-safe grid barrier: monotonic ticket counter. Each generation is
// exactly gridDim.x arrivals; base is always a multiple of gridDim.x, so all
// blocks of one generation compute the same target. Safe across graph replays.
__device__ __forceinline__ void grid_barrier()
{
    __syncthreads();
    if (threadIdx.x == 0) {
        __threadfence();
        const unsigned long long g = gridDim.x;
        unsigned long long t = atomicAdd(&g_bar, 1ULL);
        unsigned long long target = (t / g + 1ULL) * g;
        volatile unsigned long long* p = &g_bar;
        while (*p < target) __nanosleep(64);
        __threadfence();
    }
    __syncthreads();
}

// ---------------- fused kernel: qproj -> attention -> output ----------------
// grid = B*NCHUNK = 256 blocks (<= 296 co-resident at 2 blocks/SM), block=256.
__global__ void __launch_bounds__(256, 2) fused_attn(
    const float* __restrict__ query,
    const float* __restrict__ value,
    const int*   __restrict__ mask,
    const float* __restrict__ W_align,
    const float* __restrict__ b_align,
    const float* __restrict__ W_query,
    const float* __restrict__ b_query,
    const float* __restrict__ W_value,
    const float* __restrict__ b_value,
    float* __restrict__ out,
    int L)
{
    const int bid  = blockIdx.x;
    const int b    = bid >> 4;             // batch
    const int seg  = bid & 15;             // d-segment / L-chunk index
    const int tid  = threadIdx.x;
    const int warp = tid >> 5;
    const int lane = tid & 31;

    __shared__ float s_vec[D];             // query row (ph1) / combined ctx (ph3)
    __shared__ float s_q[D];               // q row (ph3)
    __shared__ int   s_idx[512];
    __shared__ int   s_pop[16], s_off[16], s_total;
    __shared__ float sm_m[8], sm_s[8];
    __shared__ float sm_ctx[8][D];
    __shared__ float s_e[NCHUNK];
    __shared__ float s_Sinv;

    // ================= Phase 1: q = query @ W_align^T + b_align ===========
    // Block (b, seg) computes q[b, seg*32 .. seg*32+32). Warp -> 4 outputs.
    for (int i = tid; i < D; i += 256) s_vec[i] = query[(size_t)b * D + i];
    __syncthreads();

    {
        const int d0 = seg * 32 + warp * 4;
        const float4* x4 = reinterpret_cast<const float4*>(s_vec);
        float4 x[4];
#pragma unroll
        for (int k = 0; k < 4; k++) x[k] = x4[lane + 32 * k];

        float acc[4] = {0.f, 0.f, 0.f, 0.f};
#pragma unroll
        for (int i = 0; i < 4; i++) {
            const float4* wrow = reinterpret_cast<const float4*>(W_align + (size_t)(d0 + i) * D);
#pragma unroll
            for (int k = 0; k < 4; k++) {
                float4 w = wrow[lane + 32 * k];
                acc[i] = fmaf(w.x, x[k].x, acc[i]); acc[i] = fmaf(w.y, x[k].y, acc[i]);
                acc[i] = fmaf(w.z, x[k].z, acc[i]); acc[i] = fmaf(w.w, x[k].w, acc[i]);
            }
        }
#pragma unroll
        for (int o = 16; o > 0; o >>= 1) {
#pragma unroll
            for (int i = 0; i < 4; i++) acc[i] += __shfl_xor_sync(0xffffffffu, acc[i], o);
        }
        if (lane < 4)
            g_q[(size_t)b * D + d0 + lane] = acc[lane] + b_align[d0 + lane];
    }

    grid_barrier();   // q visible to all blocks

    // ================= Phase 2: online-softmax over value ==================
    {
        const int RC = L / NCHUNK;          // 512
        const int l0 = seg * RC;

        // ---- compact unmasked row indices (deterministic) ----
        const int* mrow = mask + (size_t)b * L + l0;
        unsigned a0 = __ballot_sync(0xffffffffu, mrow[tid]       == 0);
        unsigned a1 = __ballot_sync(0xffffffffu, mrow[tid + 256] == 0);
        if (lane == 0) { s_pop[warp] = __popc(a0); s_pop[warp + 8] = __popc(a1); }
        __syncthreads();
        if (tid == 0) {
            int acc = 0;
#pragma unroll
            for (int i = 0; i < 16; i++) { s_off[i] = acc; acc += s_pop[i]; }
            s_total = acc;
        }
        __syncthreads();
        if ((a0 >> lane) & 1)
            s_idx[s_off[warp]     + __popc(a0 & ((1u << lane) - 1))] = warp * 32 + lane;
        if ((a1 >> lane) & 1)
            s_idx[s_off[warp + 8] + __popc(a1 & ((1u << lane) - 1))] = 256 + warp * 32 + lane;
        __syncthreads();
        const int T = s_total;

        const float4* q4 = reinterpret_cast<const float4*>(g_q + b * D);
        float4 q[4];
#pragma unroll
        for (int k = 0; k < 4; k++) q[k] = q4[lane + 32 * k];

        float m = NEG_INF, s = 0.f;
        float4 ctx[4];
#pragma unroll
        for (int k = 0; k < 4; k++) ctx[k] = make_float4(0.f, 0.f, 0.f, 0.f);

        const float* vbase = value + ((size_t)b * L + l0) * D;

        for (int t0 = warp * 4; t0 < T; t0 += 32) {
            const int n = min(4, T - t0);
            const int j0 = s_idx[t0];
            const int j1 = s_idx[t0 + (n > 1 ? 1 : 0)];
            const int j2 = s_idx[t0 + (n > 2 ? 2 : 0)];
            const int j3 = s_idx[t0 + (n > 3 ? 3 : 0)];

            const float4* p0 = reinterpret_cast<const float4*>(vbase + (size_t)j0 * D);
            const float4* p1 = reinterpret_cast<const float4*>(vbase + (size_t)j1 * D);
            const float4* p2 = reinterpret_cast<const float4*>(vbase + (size_t)j2 * D);
            const float4* p3 = reinterpret_cast<const float4*>(vbase + (size_t)j3 * D);

            float4 v0[4], v1[4], v2[4], v3[4];
#pragma unroll
            for (int k = 0; k < 4; k++) v0[k] = __ldcs(p0 + lane + 32 * k);
#pragma unroll
            for (int k = 0; k < 4; k++) v1[k] = __ldcs(p1 + lane + 32 * k);
#pragma unroll
            for (int k = 0; k < 4; k++) v2[k] = __ldcs(p2 + lane + 32 * k);
#pragma unroll
            for (int k = 0; k < 4; k++) v3[k] = __ldcs(p3 + lane + 32 * k);

            float s0 = 0.f, s1 = 0.f, s2 = 0.f, s3 = 0.f;
#pragma unroll
            for (int k = 0; k < 4; k++) {
                s0 = fmaf(v0[k].x, q[k].x, s0); s0 = fmaf(v0[k].y, q[k].y, s0);
                s0 = fmaf(v0[k].z, q[k].z, s0); s0 = fmaf(v0[k].w, q[k].w, s0);
                s1 = fmaf(v1[k].x, q[k].x, s1); s1 = fmaf(v1[k].y, q[k].y, s1);
                s1 = fmaf(v1[k].z, q[k].z, s1); s1 = fmaf(v1[k].w, q[k].w, s1);
                s2 = fmaf(v2[k].x, q[k].x, s2); s2 = fmaf(v2[k].y, q[k].y, s2);
                s2 = fmaf(v2[k].z, q[k].z, s2); s2 = fmaf(v2[k].w, q[k].w, s2);
                s3 = fmaf(v3[k].x, q[k].x, s3); s3 = fmaf(v3[k].y, q[k].y, s3);
                s3 = fmaf(v3[k].z, q[k].z, s3); s3 = fmaf(v3[k].w, q[k].w, s3);
            }
#pragma unroll
            for (int o = 16; o > 0; o >>= 1) {
                s0 += __shfl_xor_sync(0xffffffffu, s0, o);
                s1 += __shfl_xor_sync(0xffffffffu, s1, o);
                s2 += __shfl_xor_sync(0xffffffffu, s2, o);
                s3 += __shfl_xor_sync(0xffffffffu, s3, o);
            }
            if (n < 2) s1 = NEG_INF;
            if (n < 3) s2 = NEG_INF;
            if (n < 4) s3 = NEG_INF;

            const float m_new = fmaxf(fmaxf(m, fmaxf(s0, s1)), fmaxf(s2, s3));
            const float corr = __expf(m  - m_new);
            const float w0   = __expf(s0 - m_new);
            const float w1   = __expf(s1 - m_new);
            const float w2   = __expf(s2 - m_new);
            const float w3   = __expf(s3 - m_new);
            s = s * corr + w0 + w1 + w2 + w3;
#pragma unroll
            for (int k = 0; k < 4; k++) {
                ctx[k].x = ctx[k].x * corr + fmaf(w1, v1[k].x, w0 * v0[k].x)
                                           + fmaf(w3, v3[k].x, w2 * v2[k].x);
                ctx[k].y = ctx[k].y * corr + fmaf(w1, v1[k].y, w0 * v0[k].y)
                                           + fmaf(w3, v3[k].y, w2 * v2[k].y);
                ctx[k].z = ctx[k].z * corr + fmaf(w1, v1[k].z, w0 * v0[k].z)
                                           + fmaf(w3, v3[k].z, w2 * v2[k].z);
                ctx[k].w = ctx[k].w * corr + fmaf(w1, v1[k].w, w0 * v0[k].w)
                                           + fmaf(w3, v3[k].w, w2 * v2[k].w);
            }
            m = m_new;
        }

        // ---- merge the 8 warps' partials ----
        if (lane == 0) { sm_m[warp] = m; sm_s[warp] = s; }
#pragma unroll
        for (int k = 0; k < 4; k++) {
            const int i = (lane + 32 * k) * 4;
            sm_ctx[warp][i + 0] = ctx[k].x;
            sm_ctx[warp][i + 1] = ctx[k].y;
            sm_ctx[warp][i + 2] = ctx[k].z;
            sm_ctx[warp][i + 3] = ctx[k].w;
        }
        __syncthreads();

        float M = NEG_INF;
#pragma unroll
        for (int wi = 0; wi < 8; wi++) M = fmaxf(M, sm_m[wi]);

        float e[8];
#pragma unroll
        for (int wi = 0; wi < 8; wi++) e[wi] = __expf(sm_m[wi] - M);

        float o0 = 0.f, o1 = 0.f;
#pragma unroll
        for (int wi = 0; wi < 8; wi++) {
            o0 = fmaf(sm_ctx[wi][tid],       e[wi], o0);
            o1 = fmaf(sm_ctx[wi][tid + 256], e[wi], o1);
        }
        const int pidx = b * NCHUNK + seg;
        g_pctx[(size_t)pidx * D + tid]       = o0;
        g_pctx[(size_t)pidx * D + tid + 256] = o1;

        if (tid == 0) {
            float S = 0.f;
#pragma unroll
            for (int wi = 0; wi < 8; wi++) S = fmaf(sm_s[wi], e[wi], S);
            g_pm[pidx] = M;
            g_ps[pidx] = S;
        }
    }

    grid_barrier();   // all chunk partials visible

    // ================= Phase 3: combine + dual GEMV + tanh =================
    // Block (b, seg) computes out[b, seg*32 .. seg*32+32).
    {
        // combine factors (warp 0)
        if (warp == 0) {
            float mv = (lane < NCHUNK) ? g_pm[b * NCHUNK + lane] : NEG_INF;
            float M = mv;
#pragma unroll
            for (int o = 16; o > 0; o >>= 1) M = fmaxf(M, __shfl_xor_sync(0xffffffffu, M, o));
            float e  = (lane < NCHUNK) ? __expf(mv - M) : 0.f;
            float Sp = (lane < NCHUNK) ? g_ps[b * NCHUNK + lane] * e : 0.f;
#pragma unroll
            for (int o = 16; o > 0; o >>= 1) Sp += __shfl_xor_sync(0xffffffffu, Sp, o);
            if (lane < NCHUNK) s_e[lane] = e;
            if (lane == 0) s_Sinv = 1.f / Sp;
        }
        __syncthreads();

        // combine partial contexts (normalized) + cache q in smem
        const float Sinv = s_Sinv;
#pragma unroll
        for (int r = 0; r < 2; r++) {
            const int d = tid + 256 * r;
            const float* pc = g_pctx + (size_t)b * NCHUNK * D + d;
            float acc = 0.f;
#pragma unroll
            for (int c = 0; c < NCHUNK; c++)
                acc = fmaf(pc[(size_t)c * D], s_e[c], acc);
            s_vec[d] = acc * Sinv;
            s_q[d]   = g_q[(size_t)b * D + d];
        }
        __syncthreads();

        const int d0 = seg * 32 + warp * 4;
        const float4* c4 = reinterpret_cast<const float4*>(s_vec);
        const float4* q4 = reinterpret_cast<const float4*>(s_q);
        float4 cx[4], qx[4];
#pragma unroll
        for (int k = 0; k < 4; k++) { cx[k] = c4[lane + 32 * k]; qx[k] = q4[lane + 32 * k]; }

        float acc[4] = {0.f, 0.f, 0.f, 0.f};
#pragma unroll
        for (int i = 0; i < 4; i++) {
            const float4* wv = reinterpret_cast<const float4*>(W_value + (size_t)(d0 + i) * D);
            const float4* wq = reinterpret_cast<const float4*>(W_query + (size_t)(d0 + i) * D);
#pragma unroll
            for (int k = 0; k < 4; k++) {
                float4 a = wv[lane + 32 * k];
                float4 g = wq[lane + 32 * k];
                acc[i] = fmaf(a.x, cx[k].x, acc[i]); acc[i] = fmaf(a.y, cx[k].y, acc[i]);
                acc[i] = fmaf(a.z, cx[k].z, acc[i]); acc[i] = fmaf(a.w, cx[k].w, acc[i]);
                acc[i] = fmaf(g.x, qx[k].x, acc[i]); acc[i] = fmaf(g.y, qx[k].y, acc[i]);
                acc[i] = fmaf(g.z, qx[k].z, acc[i]); acc[i] = fmaf(g.w, qx[k].w, acc[i]);
            }
        }
#pragma unroll
        for (int o = 16; o > 0; o >>= 1) {
#pragma unroll
            for (int i = 0; i < 4; i++) acc[i] += __shfl_xor_sync(0xffffffffu, acc[i], o);
        }
        if (lane < 4) {
            const int d = d0 + lane;
            out[(size_t)b * D + d] = tanhf(acc[lane] + b_value[d] + b_query[d]);
        }
    }
}

// ---------------- launch ----------------
extern "C" void kernel_launch(void* const* d_in, const int* in_sizes, int n_in,
                              void* d_out, int out_size)
{
    const float* query   = (const float*)d_in[0];
    const float* value   = (const float*)d_in[1];
    const int*   mask    = (const int*)  d_in[2];
    const float* W_align = (const float*)d_in[3];
    const float* b_align = (const float*)d_in[4];
    const float* W_query = (const float*)d_in[5];
    const float* b_query = (const float*)d_in[6];
    const float* W_value = (const float*)d_in[7];
    const float* b_value = (const float*)d_in[8];
    float* out = (float*)d_out;

    const int B = in_sizes[0] / D;          // 16
    const int L = in_sizes[2] / B;          // 8192

    fused_attn<<<B * NCHUNK, 256>>>(query, value, mask,
                                    W_align, b_align, W_query, b_query,
                                    W_value, b_value, out, L);
}